// round 10
// baseline (speedup 1.0000x reference)
#include <cuda_runtime.h>
#include <cuda_bf16.h>
#include <cstdint>

#define LSEQ 2048
#define EDIM 512
#define H2 512
#define G4 2048   // 4*H2
#define NT 12
#define START_TAG 10
#define STOP_TAG 11
#define NEGV (-10000.0f)
#define SENT_BITS 0x7fc00000u   // qNaN payload; real h values are always finite
#define POLL_LIMIT (1u << 24)   // escape hatch: never triggers when co-resident
#define CRF_CHUNK 16
#define NCHUNK (LSEQ / CRF_CHUNK)   // 128

// ---------------- scratch (static device globals; no allocation) -------------
__device__ float g_xs[LSEQ * EDIM];                 // embedded inputs      (4 MB)
__device__ float g_xw[2][LSEQ * G4];                // input projections    (33 MB)
__device__ float g_hsx[2][(LSEQ + 1) * H2];         // h history, slot0=h0 (8.4 MB)
__device__ float g_feats[LSEQ * NT];
__device__ float g_crf_m[NCHUNK * NT * NT];         // chunk product matrices

// ---------------- small helpers ----------------------------------------------
__device__ __forceinline__ void fma2(unsigned long long& acc,
                                     unsigned long long a, unsigned long long b) {
    asm("fma.rn.f32x2 %0, %1, %2, %0;" : "+l"(acc) : "l"(a), "l"(b));
}
__device__ __forceinline__ float2 unpack2(unsigned long long v) {
    float2 r; asm("mov.b64 {%0, %1}, %2;" : "=f"(r.x), "=f"(r.y) : "l"(v)); return r;
}
__device__ __forceinline__ uint4 ldcg4(const uint4* p) {
    uint4 v;
    asm volatile("ld.global.cg.v4.u32 {%0,%1,%2,%3}, [%4];"
                 : "=r"(v.x), "=r"(v.y), "=r"(v.z), "=r"(v.w) : "l"(p));
    return v;
}
__device__ __forceinline__ float tanh_ap(float x) {
    float y; asm("tanh.approx.f32 %0, %1;" : "=f"(y) : "f"(x)); return y;
}
__device__ __forceinline__ float sig_ap(float x) {
    return fmaf(tanh_ap(0.5f * x), 0.5f, 0.5f);
}

// ---------------- kernel 1: sentinel-fill h history, write h0 slots ----------
__global__ void k_init_hsx(const float* __restrict__ h0) {
    int idx = blockIdx.x * blockDim.x + threadIdx.x;
    const int per = (LSEQ + 1) * H2;
    if (idx >= 2 * per) return;
    int dir = idx / per;
    int rem = idx - dir * per;
    int t = rem / H2;
    int d = rem - t * H2;
    g_hsx[dir][rem] = (t == 0) ? h0[dir * H2 + d] : __uint_as_float(SENT_BITS);
}

// ---------------- kernel 2: embedding gather ---------------------------------
__global__ void k_gather(const int* __restrict__ sent, const float* __restrict__ emb) {
    int idx = blockIdx.x * blockDim.x + threadIdx.x;   // over LSEQ * (EDIM/4)
    int t = idx >> 7;                                  // EDIM/4 = 128
    int j = idx & 127;
    int row = sent[t];
    ((float4*)g_xs)[idx] = ((const float4*)emb)[row * 128 + j];
}

// ---------------- kernel 3: input projection GEMMs  C = A * B^T + bias -------
// A = g_xs (2048x512), B = W_ih (2048x512), C = g_xw[dir] (2048x2048)
__global__ void __launch_bounds__(256) k_gemm_xw(
    const float* __restrict__ Wf, const float* __restrict__ bf,
    const float* __restrict__ Wb, const float* __restrict__ bb)
{
    int dir = blockIdx.z;
    const float* W    = dir ? Wb : Wf;
    const float* bias = dir ? bb : bf;
    float* C = g_xw[dir];
    int m0 = blockIdx.y * 64;
    int n0 = blockIdx.x * 64;

    __shared__ __align__(16) float As[16 * 72];
    __shared__ __align__(16) float Bs[16 * 72];

    int tx = threadIdx.x, ty = threadIdx.y;
    int tid = ty * 16 + tx;
    int lrow = tid >> 2;     // 0..63
    int kq   = tid & 3;      // 0..3

    float c[4][4] = {};
    for (int kt = 0; kt < 32; kt++) {
        int k0 = kt * 16;
        float4 a = *(const float4*)&g_xs[(m0 + lrow) * EDIM + k0 + kq * 4];
        float4 b = *(const float4*)&W[(n0 + lrow) * EDIM + k0 + kq * 4];
        __syncthreads();
        As[(kq * 4 + 0) * 72 + lrow] = a.x;
        As[(kq * 4 + 1) * 72 + lrow] = a.y;
        As[(kq * 4 + 2) * 72 + lrow] = a.z;
        As[(kq * 4 + 3) * 72 + lrow] = a.w;
        Bs[(kq * 4 + 0) * 72 + lrow] = b.x;
        Bs[(kq * 4 + 1) * 72 + lrow] = b.y;
        Bs[(kq * 4 + 2) * 72 + lrow] = b.z;
        Bs[(kq * 4 + 3) * 72 + lrow] = b.w;
        __syncthreads();
        #pragma unroll
        for (int kk = 0; kk < 16; kk++) {
            float4 av = *(const float4*)&As[kk * 72 + ty * 4];
            float4 bv = *(const float4*)&Bs[kk * 72 + tx * 4];
            c[0][0] += av.x * bv.x; c[0][1] += av.x * bv.y; c[0][2] += av.x * bv.z; c[0][3] += av.x * bv.w;
            c[1][0] += av.y * bv.x; c[1][1] += av.y * bv.y; c[1][2] += av.y * bv.z; c[1][3] += av.y * bv.w;
            c[2][0] += av.z * bv.x; c[2][1] += av.z * bv.y; c[2][2] += av.z * bv.z; c[2][3] += av.z * bv.w;
            c[3][0] += av.w * bv.x; c[3][1] += av.w * bv.y; c[3][2] += av.w * bv.z; c[3][3] += av.w * bv.w;
        }
    }
    float4 bv = *(const float4*)&bias[n0 + tx * 4];
    #pragma unroll
    for (int i = 0; i < 4; i++) {
        float4 o = make_float4(c[i][0] + bv.x, c[i][1] + bv.y, c[i][2] + bv.z, c[i][3] + bv.w);
        *(float4*)&C[(m0 + ty * 4 + i) * G4 + n0 + tx * 4] = o;
    }
}

// ---------------- kernel 4: persistent bidirectional LSTM recurrence ---------
// 64 CTAs: blockIdx/32 = direction, 32 CTAs per direction, 16 h-dims each.
// W_hh slice (64 gate rows x 512) lives in registers. h handoff between CTAs
// is sentinel-word message passing through L2 (single 32-bit payloads: no
// fences needed; the loaded value IS the message). Poll is BOUNDED: if
// co-residency ever fails, we proceed with whatever is there (bench then
// reports a correctness failure WITH timing/ncu data instead of hanging).
__global__ void __launch_bounds__(512, 1) k_lstm(
    const float* __restrict__ Whf, const float* __restrict__ Whb,
    const float* __restrict__ c0)
{
    int dir = blockIdx.x >> 5;
    int cb  = blockIdx.x & 31;
    const float* W  = dir ? Whb : Whf;
    const float* xw = g_xw[dir];
    float* hsx = g_hsx[dir];

    int tid = threadIdx.x;
    int row = tid >> 3;            // 0..63 (gate row within slice)
    int kc  = tid & 7;
    int k0  = kc << 6;             // 64-wide k chunk
    int g = row >> 4, d = row & 15;
    int D0 = cb << 4;              // first h-dim owned
    int grow = (g << 9) + D0 + d;  // global gate row

    // weights -> registers: 64 floats as 32 packed f32x2 words
    unsigned long long w[32];
    {
        const ulonglong2* wp = (const ulonglong2*)(W + grow * H2 + k0);
        #pragma unroll
        for (int i = 0; i < 16; i++) { ulonglong2 v = wp[i]; w[2*i] = v.x; w[2*i+1] = v.y; }
    }

    __shared__ __align__(16) float h_sm[H2];
    __shared__ float rowsum[64];
    __shared__ float pre_sm[64];
    __shared__ float c_sm[16];
    if (tid < 16) c_sm[tid] = c0[dir * H2 + D0 + tid];

    int pg = tid >> 4, pd = tid & 15;            // for tid<64 prefetch mapping
    int pgrow = (pg << 9) + D0 + pd;

    for (int t = 0; t < LSEQ; t++) {
        __syncthreads();                         // guard smem reuse across steps
        int xrow = dir ? (LSEQ - 1 - t) : t;
        if (tid < 64) pre_sm[tid] = __ldg(&xw[xrow * G4 + pgrow]);  // off poll path
        if (tid < 128) {
            const uint4* src = (const uint4*)(hsx + t * H2) + tid;
            uint4 v;
            unsigned int it = 0;
            do {
                v = ldcg4(src);
                if (++it >= POLL_LIMIT) break;   // escape hatch (never taken normally)
            } while (v.x == SENT_BITS || v.y == SENT_BITS ||
                     v.z == SENT_BITS || v.w == SENT_BITS);
            ((uint4*)h_sm)[tid] = v;
        }
        __syncthreads();

        // partial dot: 64 MACs as 32 packed f32x2 FMAs against register weights
        unsigned long long acc0 = 0ull, acc1 = 0ull;
        const ulonglong2* hp = (const ulonglong2*)(h_sm + k0);
        #pragma unroll
        for (int i = 0; i < 16; i++) {
            ulonglong2 hv = hp[i];
            fma2(acc0, w[2*i],   hv.x);
            fma2(acc1, w[2*i+1], hv.y);
        }
        float2 a0 = unpack2(acc0), a1 = unpack2(acc1);
        float s = (a0.x + a0.y) + (a1.x + a1.y);
        s += __shfl_xor_sync(0xffffffffu, s, 1);
        s += __shfl_xor_sync(0xffffffffu, s, 2);
        s += __shfl_xor_sync(0xffffffffu, s, 4);
        if (kc == 0) rowsum[row] = s;
        __syncthreads();

        if (tid < 16) {
            float pi = pre_sm[tid]      + rowsum[tid];
            float pf = pre_sm[16 + tid] + rowsum[16 + tid];
            float pgt= pre_sm[32 + tid] + rowsum[32 + tid];
            float po = pre_sm[48 + tid] + rowsum[48 + tid];
            float ii = sig_ap(pi), ff = sig_ap(pf), gg = tanh_ap(pgt), oo = sig_ap(po);
            float cc = fmaf(ff, c_sm[tid], ii * gg);
            c_sm[tid] = cc;
            float hh = oo * tanh_ap(cc);
            __stcg(&hsx[(t + 1) * H2 + D0 + tid], hh);   // publish (never NaN)
        }
    }
}

// ---------------- kernel 5: feats = [hf;hb] @ W_out^T + b_out ----------------
__global__ void __launch_bounds__(384) k_feats(const float* __restrict__ Wout,
                                               const float* __restrict__ bout)
{
    int t0 = blockIdx.x * 4;
    int tid = threadIdx.x;
    int wrp = tid >> 5;       // 0..11 = output tag
    int lane = tid & 31;
    __shared__ float W_sm[NT * 512];
    __shared__ float h_sm[512];
    float pacc[4] = {0.f, 0.f, 0.f, 0.f};

    for (int half = 0; half < 2; half++) {
        __syncthreads();
        #pragma unroll
        for (int i = 0; i < 16; i++) {
            int idx = tid + i * 384;
            W_sm[idx] = Wout[(idx >> 9) * 1024 + (half << 9) + (idx & 511)];
        }
        for (int tt = 0; tt < 4; tt++) {
            int t = t0 + tt;
            __syncthreads();
            int hrow = half ? (LSEQ - t) : (t + 1);    // hb[t] = hsx_b[L - t]
            const float* hsrc = g_hsx[half] + hrow * H2;
            for (int j = tid; j < 512; j += 384) h_sm[j] = hsrc[j];
            __syncthreads();
            float p = 0.f;
            #pragma unroll
            for (int k = lane; k < 512; k += 32) p += h_sm[k] * W_sm[wrp * 512 + k];
            pacc[tt] += p;
        }
    }
    #pragma unroll
    for (int tt = 0; tt < 4; tt++) {
        float p = pacc[tt];
        #pragma unroll
        for (int off = 16; off; off >>= 1) p += __shfl_down_sync(0xffffffffu, p, off);
        if (lane == 0) g_feats[(t0 + tt) * NT + wrp] = p + bout[wrp];
    }
}

// ---------------- kernel 6a: CRF chunk products (log-semiring scan, up-sweep)
// Chunk c covers steps [16c, 16c+16). Block computes
//   M_c = A_{16c+15} (x) ... (x) A_{16c},  A_t[i,j] = trans[i,j] + feat_t[i]
// 144 threads, thread = entry (i,j). Update identity:
//   (A_t (x) M)[i,j] = feat_t[i] + LSE_k(trans[i,k] + M[k,j])
__global__ void k_crf_chunks(const float* __restrict__ trans) {
    int c = blockIdx.x;
    int tid = threadIdx.x;            // 0..143
    int i = tid / NT, j = tid - i * NT;
    __shared__ float Ma[NT * NT], Mb[NT * NT];
    float trow[NT];
    #pragma unroll
    for (int k = 0; k < NT; k++) trow[k] = trans[i * NT + k];

    int t0 = c * CRF_CHUNK;
    Ma[tid] = trow[j] + __ldg(&g_feats[t0 * NT + i]);   // M = A_{t0}
    __syncthreads();

    float* cur = Ma; float* nxt = Mb;
    for (int s = 1; s < CRF_CHUNK; s++) {
        float feat_i = __ldg(&g_feats[(t0 + s) * NT + i]);
        float m = -3.4e38f, vals[NT];
        #pragma unroll
        for (int k = 0; k < NT; k++) { vals[k] = trow[k] + cur[k * NT + j]; m = fmaxf(m, vals[k]); }
        float ssum = 0.f;
        #pragma unroll
        for (int k = 0; k < NT; k++) ssum += __expf(vals[k] - m);
        nxt[tid] = feat_i + m + __logf(ssum);
        __syncthreads();
        float* tmp = cur; cur = nxt; nxt = tmp;
    }
    g_crf_m[c * NT * NT + tid] = cur[tid];
}

// ---------------- kernel 6b: fold chunk matrices into fv, terminal LSE -------
__global__ void k_crf_fold(const float* __restrict__ trans, float* __restrict__ out) {
    int lane = threadIdx.x;
    bool act = lane < NT;
    __shared__ float fv[NT];
    if (act) fv[lane] = (lane == START_TAG) ? 0.f : NEGV;
    __syncwarp();
    for (int c = 0; c < NCHUNK; c++) {
        float nv = 0.f;
        if (act) {
            const float* M = &g_crf_m[c * NT * NT + lane * NT];   // row `lane`
            float m = -3.4e38f, vals[NT];
            #pragma unroll
            for (int j = 0; j < NT; j++) { vals[j] = __ldg(&M[j]) + fv[j]; m = fmaxf(m, vals[j]); }
            float s = 0.f;
            #pragma unroll
            for (int j = 0; j < NT; j++) s += __expf(vals[j] - m);
            nv = m + __logf(s);
        }
        __syncwarp();
        if (act) fv[lane] = nv;
        __syncwarp();
    }
    if (lane == 0) {
        float m = -3.4e38f, vals[NT];
        #pragma unroll
        for (int j = 0; j < NT; j++) { vals[j] = fv[j] + trans[STOP_TAG * NT + j]; m = fmaxf(m, vals[j]); }
        float s = 0.f;
        #pragma unroll
        for (int j = 0; j < NT; j++) s += __expf(vals[j] - m);
        out[0] = m + __logf(s);
    }
}

// ---------------- launcher ----------------------------------------------------
extern "C" void kernel_launch(void* const* d_in, const int* in_sizes, int n_in,
                              void* d_out, int out_size)
{
    const int*   sentence = (const int*)  d_in[0];
    const float* emb      = (const float*)d_in[1];
    const float* W_ih_f   = (const float*)d_in[2];
    const float* W_hh_f   = (const float*)d_in[3];
    const float* b_f      = (const float*)d_in[4];
    const float* W_ih_b   = (const float*)d_in[5];
    const float* W_hh_b   = (const float*)d_in[6];
    const float* b_b      = (const float*)d_in[7];
    const float* W_out    = (const float*)d_in[8];
    const float* b_out    = (const float*)d_in[9];
    const float* trans    = (const float*)d_in[10];
    const float* h0       = (const float*)d_in[11];
    const float* c0       = (const float*)d_in[12];
    float* out = (float*)d_out;

    (void)in_sizes; (void)n_in; (void)out_size;

    // 1. sentinel-fill h history (both dirs) + write h0 into slot 0
    k_init_hsx<<<(2 * (LSEQ + 1) * H2 + 255) / 256, 256>>>(h0);
    // 2. embedding gather
    k_gather<<<(LSEQ * (EDIM / 4)) / 256, 256>>>(sentence, emb);
    // 3. input projections for both directions
    k_gemm_xw<<<dim3(32, 32, 2), dim3(16, 16)>>>(W_ih_f, b_f, W_ih_b, b_b);
    // 4. persistent bidirectional recurrence (64 co-resident CTAs)
    k_lstm<<<64, 512>>>(W_hh_f, W_hh_b, c0);
    // 5. output projection
    k_feats<<<LSEQ / 4, 384>>>(W_out, b_out);
    // 6. CRF forward: parallel chunk products, then sequential fold
    k_crf_chunks<<<NCHUNK, NT * NT>>>(trans);
    k_crf_fold<<<1, 32>>>(trans, out);
}

// round 14
// speedup vs baseline: 3.3231x; 3.3231x over previous
#include <cuda_runtime.h>
#include <cuda_bf16.h>
#include <cstdint>

#define LSEQ 2048
#define EDIM 512
#define H2 512
#define G4 2048   // 4*H2
#define NT 12
#define START_TAG 10
#define STOP_TAG 11
#define NEGV (-10000.0f)
#define SENT_BITS 0x7fc00000u   // qNaN payload; real h values are always finite
#define POLL_LIMIT (1u << 24)   // escape hatch: never triggers when co-resident
#define CRF_CHUNK 16
#define NCHUNK (LSEQ / CRF_CHUNK)   // 128
#define CPAD 68                  // padded chunk stride (floats): conflict-free LDS

// ---------------- scratch (static device globals; no allocation) -------------
__device__ float g_xs[LSEQ * EDIM];                 // embedded inputs      (4 MB)
__device__ float g_xw[2][LSEQ * G4];                // input projections    (33 MB)
__device__ float g_hsx[2][(LSEQ + 1) * H2];         // h history, slot0=h0 (8.4 MB)
__device__ float g_feats[LSEQ * NT];
__device__ float g_crf_m[NCHUNK * NT * NT];         // chunk product matrices

// ---------------- small helpers ----------------------------------------------
__device__ __forceinline__ void fma2(unsigned long long& acc,
                                     unsigned long long a, unsigned long long b) {
    asm("fma.rn.f32x2 %0, %1, %2, %0;" : "+l"(acc) : "l"(a), "l"(b));
}
__device__ __forceinline__ float2 unpack2(unsigned long long v) {
    float2 r; asm("mov.b64 {%0, %1}, %2;" : "=f"(r.x), "=f"(r.y) : "l"(v)); return r;
}
__device__ __forceinline__ uint4 ldcg4(const uint4* p) {
    uint4 v;
    asm volatile("ld.global.cg.v4.u32 {%0,%1,%2,%3}, [%4];"
                 : "=r"(v.x), "=r"(v.y), "=r"(v.z), "=r"(v.w) : "l"(p));
    return v;
}
__device__ __forceinline__ float tanh_ap(float x) {
    float y; asm("tanh.approx.f32 %0, %1;" : "=f"(y) : "f"(x)); return y;
}
__device__ __forceinline__ float sig_ap(float x) {
    return fmaf(tanh_ap(0.5f * x), 0.5f, 0.5f);
}

// ---------------- kernel 1: sentinel-fill h history, write h0 slots ----------
__global__ void k_init_hsx(const float* __restrict__ h0) {
    int idx = blockIdx.x * blockDim.x + threadIdx.x;
    const int per = (LSEQ + 1) * H2;
    if (idx >= 2 * per) return;
    int dir = idx / per;
    int rem = idx - dir * per;
    int t = rem / H2;
    int d = rem - t * H2;
    g_hsx[dir][rem] = (t == 0) ? h0[dir * H2 + d] : __uint_as_float(SENT_BITS);
}

// ---------------- kernel 2: embedding gather ---------------------------------
__global__ void k_gather(const int* __restrict__ sent, const float* __restrict__ emb) {
    int idx = blockIdx.x * blockDim.x + threadIdx.x;   // over LSEQ * (EDIM/4)
    int t = idx >> 7;                                  // EDIM/4 = 128
    int j = idx & 127;
    int row = sent[t];
    ((float4*)g_xs)[idx] = ((const float4*)emb)[row * 128 + j];
}

// ---------------- kernel 3: input projection GEMMs  C = A * B^T + bias -------
__global__ void __launch_bounds__(256) k_gemm_xw(
    const float* __restrict__ Wf, const float* __restrict__ bf,
    const float* __restrict__ Wb, const float* __restrict__ bb)
{
    int dir = blockIdx.z;
    const float* W    = dir ? Wb : Wf;
    const float* bias = dir ? bb : bf;
    float* C = g_xw[dir];
    int m0 = blockIdx.y * 64;
    int n0 = blockIdx.x * 64;

    __shared__ __align__(16) float As[16 * 72];
    __shared__ __align__(16) float Bs[16 * 72];

    int tx = threadIdx.x, ty = threadIdx.y;
    int tid = ty * 16 + tx;
    int lrow = tid >> 2;     // 0..63
    int kq   = tid & 3;      // 0..3

    float c[4][4] = {};
    for (int kt = 0; kt < 32; kt++) {
        int k0 = kt * 16;
        float4 a = *(const float4*)&g_xs[(m0 + lrow) * EDIM + k0 + kq * 4];
        float4 b = *(const float4*)&W[(n0 + lrow) * EDIM + k0 + kq * 4];
        __syncthreads();
        As[(kq * 4 + 0) * 72 + lrow] = a.x;
        As[(kq * 4 + 1) * 72 + lrow] = a.y;
        As[(kq * 4 + 2) * 72 + lrow] = a.z;
        As[(kq * 4 + 3) * 72 + lrow] = a.w;
        Bs[(kq * 4 + 0) * 72 + lrow] = b.x;
        Bs[(kq * 4 + 1) * 72 + lrow] = b.y;
        Bs[(kq * 4 + 2) * 72 + lrow] = b.z;
        Bs[(kq * 4 + 3) * 72 + lrow] = b.w;
        __syncthreads();
        #pragma unroll
        for (int kk = 0; kk < 16; kk++) {
            float4 av = *(const float4*)&As[kk * 72 + ty * 4];
            float4 bv = *(const float4*)&Bs[kk * 72 + tx * 4];
            c[0][0] += av.x * bv.x; c[0][1] += av.x * bv.y; c[0][2] += av.x * bv.z; c[0][3] += av.x * bv.w;
            c[1][0] += av.y * bv.x; c[1][1] += av.y * bv.y; c[1][2] += av.y * bv.z; c[1][3] += av.y * bv.w;
            c[2][0] += av.z * bv.x; c[2][1] += av.z * bv.y; c[2][2] += av.z * bv.z; c[2][3] += av.z * bv.w;
            c[3][0] += av.w * bv.x; c[3][1] += av.w * bv.y; c[3][2] += av.w * bv.z; c[3][3] += av.w * bv.w;
        }
    }
    float4 bv = *(const float4*)&bias[n0 + tx * 4];
    #pragma unroll
    for (int i = 0; i < 4; i++) {
        float4 o = make_float4(c[i][0] + bv.x, c[i][1] + bv.y, c[i][2] + bv.z, c[i][3] + bv.w);
        *(float4*)&C[(m0 + ty * 4 + i) * G4 + n0 + tx * 4] = o;
    }
}

// ---------------- kernel 4: persistent bidirectional LSTM recurrence ---------
// EXACT v1 (R10, passed @10115us) control flow: 3 barriers/step, single-probe
// poll, pre_sm staging. Only deltas vs v1: (a) padded h_sm layout (CPAD=68)
// making the FMA-loop LDS.128 conflict-free; (b) per-gate c state in registers.
__global__ void __launch_bounds__(512, 1) k_lstm(
    const float* __restrict__ Whf, const float* __restrict__ Whb,
    const float* __restrict__ c0)
{
    int dir = blockIdx.x >> 5;
    int cb  = blockIdx.x & 31;
    const float* W  = dir ? Whb : Whf;
    const float* xw = g_xw[dir];
    float* hsx = g_hsx[dir];

    int tid = threadIdx.x;
    int row = tid >> 3;            // 0..63 (gate row within slice)
    int kc  = tid & 7;
    int k0f = kc << 6;             // chunk start (logical float index)
    int g = row >> 4, d = row & 15;
    int D0 = cb << 4;              // first h-dim owned
    int grow = (g << 9) + D0 + d;  // global gate row

    // weights -> registers: 64 floats as 32 packed f32x2 words
    unsigned long long w[32];
    {
        const ulonglong2* wp = (const ulonglong2*)(W + grow * H2 + k0f);
        #pragma unroll
        for (int i = 0; i < 16; i++) { ulonglong2 v = wp[i]; w[2*i] = v.x; w[2*i+1] = v.y; }
    }

    __shared__ __align__(16) float h_sm[8 * CPAD];   // padded: conflict-free reads
    __shared__ float rowsum[64];
    __shared__ float pre_sm[64];

    float creg = 0.f;
    if (tid < 16) creg = c0[dir * H2 + D0 + tid];

    int pg = tid >> 4, pd = tid & 15;            // tid<64 prefetch mapping
    int pgrow = (pg << 9) + D0 + pd;
    int pchunk = tid >> 4, pj = tid & 15;        // tid<128 poller mapping

    for (int t = 0; t < LSEQ; t++) {
        __syncthreads();                         // BAR0: guard smem reuse
        int xrow = dir ? (LSEQ - 1 - t) : t;
        if (tid < 64) pre_sm[tid] = __ldg(&xw[xrow * G4 + pgrow]);  // off poll path
        if (tid < 128) {
            const uint4* src = (const uint4*)(hsx + t * H2) + tid;
            uint4 v;
            unsigned int it = 0;
            do {
                v = ldcg4(src);
                if (++it >= POLL_LIMIT) break;   // escape hatch (never taken normally)
            } while (v.x == SENT_BITS || v.y == SENT_BITS ||
                     v.z == SENT_BITS || v.w == SENT_BITS);
            *(uint4*)&h_sm[pchunk * CPAD + pj * 4] = v;
        }
        __syncthreads();                         // BAR1: h staged

        // partial dot: 64 MACs as 32 packed f32x2 FMAs against register weights
        unsigned long long acc0 = 0ull, acc1 = 0ull;
        const ulonglong2* hp = (const ulonglong2*)&h_sm[kc * CPAD];
        #pragma unroll
        for (int i = 0; i < 16; i++) {
            ulonglong2 hv = hp[i];
            fma2(acc0, w[2*i],   hv.x);
            fma2(acc1, w[2*i+1], hv.y);
        }
        float2 a0 = unpack2(acc0), a1 = unpack2(acc1);
        float s = (a0.x + a0.y) + (a1.x + a1.y);
        s += __shfl_xor_sync(0xffffffffu, s, 1);
        s += __shfl_xor_sync(0xffffffffu, s, 2);
        s += __shfl_xor_sync(0xffffffffu, s, 4);
        if (kc == 0) rowsum[row] = s;
        __syncthreads();                         // BAR2: rowsum ready

        if (tid < 16) {
            float pi = pre_sm[tid]      + rowsum[tid];
            float pf = pre_sm[16 + tid] + rowsum[16 + tid];
            float pgt= pre_sm[32 + tid] + rowsum[32 + tid];
            float po = pre_sm[48 + tid] + rowsum[48 + tid];
            float ii = sig_ap(pi), ff = sig_ap(pf), gg = tanh_ap(pgt), oo = sig_ap(po);
            creg = fmaf(ff, creg, ii * gg);
            float hh = oo * tanh_ap(creg);
            __stcg(&hsx[(t + 1) * H2 + D0 + tid], hh);   // publish (never NaN)
        }
    }
}

// ---------------- kernel 5: feats = [hf;hb] @ W_out^T + b_out ----------------
__global__ void __launch_bounds__(384) k_feats(const float* __restrict__ Wout,
                                               const float* __restrict__ bout)
{
    int t0 = blockIdx.x * 4;
    int tid = threadIdx.x;
    int wrp = tid >> 5;       // 0..11 = output tag
    int lane = tid & 31;
    __shared__ float W_sm[NT * 512];
    __shared__ float h_sm[512];
    float pacc[4] = {0.f, 0.f, 0.f, 0.f};

    for (int half = 0; half < 2; half++) {
        __syncthreads();
        #pragma unroll
        for (int i = 0; i < 16; i++) {
            int idx = tid + i * 384;
            W_sm[idx] = Wout[(idx >> 9) * 1024 + (half << 9) + (idx & 511)];
        }
        for (int tt = 0; tt < 4; tt++) {
            int t = t0 + tt;
            __syncthreads();
            int hrow = half ? (LSEQ - t) : (t + 1);    // hb[t] = hsx_b[L - t]
            const float* hsrc = g_hsx[half] + hrow * H2;
            for (int j = tid; j < 512; j += 384) h_sm[j] = hsrc[j];
            __syncthreads();
            float p = 0.f;
            #pragma unroll
            for (int k = lane; k < 512; k += 32) p += h_sm[k] * W_sm[wrp * 512 + k];
            pacc[tt] += p;
        }
    }
    #pragma unroll
    for (int tt = 0; tt < 4; tt++) {
        float p = pacc[tt];
        #pragma unroll
        for (int off = 16; off; off >>= 1) p += __shfl_down_sync(0xffffffffu, p, off);
        if (lane == 0) g_feats[(t0 + tt) * NT + wrp] = p + bout[wrp];
    }
}

// ---------------- kernel 6a: CRF chunk products (log-semiring scan) ----------
__global__ void k_crf_chunks(const float* __restrict__ trans) {
    int c = blockIdx.x;
    int tid = threadIdx.x;            // 0..143
    int i = tid / NT, j = tid - i * NT;
    __shared__ float Ma[NT * NT], Mb[NT * NT];
    float trow[NT];
    #pragma unroll
    for (int k = 0; k < NT; k++) trow[k] = trans[i * NT + k];

    int t0 = c * CRF_CHUNK;
    Ma[tid] = trow[j] + __ldg(&g_feats[t0 * NT + i]);   // M = A_{t0}
    __syncthreads();

    float* cur = Ma; float* nxt = Mb;
    for (int s = 1; s < CRF_CHUNK; s++) {
        float feat_i = __ldg(&g_feats[(t0 + s) * NT + i]);
        float m = -3.4e38f, vals[NT];
        #pragma unroll
        for (int k = 0; k < NT; k++) { vals[k] = trow[k] + cur[k * NT + j]; m = fmaxf(m, vals[k]); }
        float ssum = 0.f;
        #pragma unroll
        for (int k = 0; k < NT; k++) ssum += __expf(vals[k] - m);
        nxt[tid] = feat_i + m + __logf(ssum);
        __syncthreads();
        float* tmp = cur; cur = nxt; nxt = tmp;
    }
    g_crf_m[c * NT * NT + tid] = cur[tid];
}

// ---------------- kernel 6b: fold chunk matrices into fv, terminal LSE -------
__global__ void k_crf_fold(const float* __restrict__ trans, float* __restrict__ out) {
    int lane = threadIdx.x;
    bool act = lane < NT;
    __shared__ float fv[NT];
    if (act) fv[lane] = (lane == START_TAG) ? 0.f : NEGV;
    __syncwarp();
    for (int c = 0; c < NCHUNK; c++) {
        float nv = 0.f;
        if (act) {
            const float* M = &g_crf_m[c * NT * NT + lane * NT];   // row `lane`
            float m = -3.4e38f, vals[NT];
            #pragma unroll
            for (int j = 0; j < NT; j++) { vals[j] = __ldg(&M[j]) + fv[j]; m = fmaxf(m, vals[j]); }
            float s = 0.f;
            #pragma unroll
            for (int j = 0; j < NT; j++) s += __expf(vals[j] - m);
            nv = m + __logf(s);
        }
        __syncwarp();
        if (act) fv[lane] = nv;
        __syncwarp();
    }
    if (lane == 0) {
        float m = -3.4e38f, vals[NT];
        #pragma unroll
        for (int j = 0; j < NT; j++) { vals[j] = fv[j] + trans[STOP_TAG * NT + j]; m = fmaxf(m, vals[j]); }
        float s = 0.f;
        #pragma unroll
        for (int j = 0; j < NT; j++) s += __expf(vals[j] - m);
        out[0] = m + __logf(s);
    }
}

// ---------------- launcher ----------------------------------------------------
extern "C" void kernel_launch(void* const* d_in, const int* in_sizes, int n_in,
                              void* d_out, int out_size)
{
    const int*   sentence = (const int*)  d_in[0];
    const float* emb      = (const float*)d_in[1];
    const float* W_ih_f   = (const float*)d_in[2];
    const float* W_hh_f   = (const float*)d_in[3];
    const float* b_f      = (const float*)d_in[4];
    const float* W_ih_b   = (const float*)d_in[5];
    const float* W_hh_b   = (const float*)d_in[6];
    const float* b_b      = (const float*)d_in[7];
    const float* W_out    = (const float*)d_in[8];
    const float* b_out    = (const float*)d_in[9];
    const float* trans    = (const float*)d_in[10];
    const float* h0       = (const float*)d_in[11];
    const float* c0       = (const float*)d_in[12];
    float* out = (float*)d_out;

    (void)in_sizes; (void)n_in; (void)out_size;

    // 1. sentinel-fill h history (both dirs) + write h0 into slot 0
    k_init_hsx<<<(2 * (LSEQ + 1) * H2 + 255) / 256, 256>>>(h0);
    // 2. embedding gather
    k_gather<<<(LSEQ * (EDIM / 4)) / 256, 256>>>(sentence, emb);
    // 3. input projections for both directions
    k_gemm_xw<<<dim3(32, 32, 2), dim3(16, 16)>>>(W_ih_f, b_f, W_ih_b, b_b);
    // 4. persistent bidirectional recurrence (64 co-resident CTAs)
    k_lstm<<<64, 512>>>(W_hh_f, W_hh_b, c0);
    // 5. output projection
    k_feats<<<LSEQ / 4, 384>>>(W_out, b_out);
    // 6. CRF forward: parallel chunk products, then sequential fold
    k_crf_chunks<<<NCHUNK, NT * NT>>>(trans);
    k_crf_fold<<<1, 32>>>(trans, out);
}

// round 15
// speedup vs baseline: 3.4986x; 1.0528x over previous
#include <cuda_runtime.h>
#include <cuda_bf16.h>
#include <cstdint>

#define LSEQ 2048
#define EDIM 512
#define H2 512
#define G4 2048   // 4*H2
#define NT 12
#define START_TAG 10
#define STOP_TAG 11
#define NEGV (-10000.0f)
#define SENT_BITS 0x7fc00000u   // qNaN payload; real h values are always finite
#define POLL_LIMIT (1u << 24)   // escape hatch: never triggers when co-resident
#define CRF_CHUNK 16
#define NCHUNK (LSEQ / CRF_CHUNK)   // 128
#define CPAD 68                  // padded chunk stride (floats): conflict-free LDS

// ---------------- scratch (static device globals; no allocation) -------------
__device__ float g_xs[LSEQ * EDIM];                 // embedded inputs      (4 MB)
__device__ float g_xw[2][LSEQ * G4];                // input projections    (33 MB)
__device__ float g_hsx[2][(LSEQ + 1) * H2];         // h history, slot0=h0 (8.4 MB)
__device__ float g_feats[LSEQ * NT];
__device__ float g_crf_m[NCHUNK * NT * NT];         // chunk product matrices

// ---------------- small helpers ----------------------------------------------
__device__ __forceinline__ void fma2(unsigned long long& acc,
                                     unsigned long long a, unsigned long long b) {
    asm("fma.rn.f32x2 %0, %1, %2, %0;" : "+l"(acc) : "l"(a), "l"(b));
}
__device__ __forceinline__ float2 unpack2(unsigned long long v) {
    float2 r; asm("mov.b64 {%0, %1}, %2;" : "=f"(r.x), "=f"(r.y) : "l"(v)); return r;
}
__device__ __forceinline__ uint4 ldcg4(const uint4* p) {
    uint4 v;
    asm volatile("ld.global.cg.v4.u32 {%0,%1,%2,%3}, [%4];"
                 : "=r"(v.x), "=r"(v.y), "=r"(v.z), "=r"(v.w) : "l"(p));
    return v;
}
__device__ __forceinline__ float tanh_ap(float x) {
    float y; asm("tanh.approx.f32 %0, %1;" : "=f"(y) : "f"(x)); return y;
}
__device__ __forceinline__ float sig_ap(float x) {
    return fmaf(tanh_ap(0.5f * x), 0.5f, 0.5f);
}

// ---------------- kernel 1: sentinel-fill h history, write h0 slots ----------
__global__ void k_init_hsx(const float* __restrict__ h0) {
    int idx = blockIdx.x * blockDim.x + threadIdx.x;
    const int per = (LSEQ + 1) * H2;
    if (idx >= 2 * per) return;
    int dir = idx / per;
    int rem = idx - dir * per;
    int t = rem / H2;
    int d = rem - t * H2;
    g_hsx[dir][rem] = (t == 0) ? h0[dir * H2 + d] : __uint_as_float(SENT_BITS);
}

// ---------------- kernel 2: embedding gather ---------------------------------
__global__ void k_gather(const int* __restrict__ sent, const float* __restrict__ emb) {
    int idx = blockIdx.x * blockDim.x + threadIdx.x;   // over LSEQ * (EDIM/4)
    int t = idx >> 7;                                  // EDIM/4 = 128
    int j = idx & 127;
    int row = sent[t];
    ((float4*)g_xs)[idx] = ((const float4*)emb)[row * 128 + j];
}

// ---------------- kernel 3: input projection GEMMs  C = A * B^T + bias -------
__global__ void __launch_bounds__(256) k_gemm_xw(
    const float* __restrict__ Wf, const float* __restrict__ bf,
    const float* __restrict__ Wb, const float* __restrict__ bb)
{
    int dir = blockIdx.z;
    const float* W    = dir ? Wb : Wf;
    const float* bias = dir ? bb : bf;
    float* C = g_xw[dir];
    int m0 = blockIdx.y * 64;
    int n0 = blockIdx.x * 64;

    __shared__ __align__(16) float As[16 * 72];
    __shared__ __align__(16) float Bs[16 * 72];

    int tx = threadIdx.x, ty = threadIdx.y;
    int tid = ty * 16 + tx;
    int lrow = tid >> 2;     // 0..63
    int kq   = tid & 3;      // 0..3

    float c[4][4] = {};
    for (int kt = 0; kt < 32; kt++) {
        int k0 = kt * 16;
        float4 a = *(const float4*)&g_xs[(m0 + lrow) * EDIM + k0 + kq * 4];
        float4 b = *(const float4*)&W[(n0 + lrow) * EDIM + k0 + kq * 4];
        __syncthreads();
        As[(kq * 4 + 0) * 72 + lrow] = a.x;
        As[(kq * 4 + 1) * 72 + lrow] = a.y;
        As[(kq * 4 + 2) * 72 + lrow] = a.z;
        As[(kq * 4 + 3) * 72 + lrow] = a.w;
        Bs[(kq * 4 + 0) * 72 + lrow] = b.x;
        Bs[(kq * 4 + 1) * 72 + lrow] = b.y;
        Bs[(kq * 4 + 2) * 72 + lrow] = b.z;
        Bs[(kq * 4 + 3) * 72 + lrow] = b.w;
        __syncthreads();
        #pragma unroll
        for (int kk = 0; kk < 16; kk++) {
            float4 av = *(const float4*)&As[kk * 72 + ty * 4];
            float4 bv = *(const float4*)&Bs[kk * 72 + tx * 4];
            c[0][0] += av.x * bv.x; c[0][1] += av.x * bv.y; c[0][2] += av.x * bv.z; c[0][3] += av.x * bv.w;
            c[1][0] += av.y * bv.x; c[1][1] += av.y * bv.y; c[1][2] += av.y * bv.z; c[1][3] += av.y * bv.w;
            c[2][0] += av.z * bv.x; c[2][1] += av.z * bv.y; c[2][2] += av.z * bv.z; c[2][3] += av.z * bv.w;
            c[3][0] += av.w * bv.x; c[3][1] += av.w * bv.y; c[3][2] += av.w * bv.z; c[3][3] += av.w * bv.w;
        }
    }
    float4 bv = *(const float4*)&bias[n0 + tx * 4];
    #pragma unroll
    for (int i = 0; i < 4; i++) {
        float4 o = make_float4(c[i][0] + bv.x, c[i][1] + bv.y, c[i][2] + bv.z, c[i][3] + bv.w);
        *(float4*)&C[(m0 + ty * 4 + i) * G4 + n0 + tx * 4] = o;
    }
}

// ---------------- kernel 4: persistent bidirectional LSTM recurrence ---------
// Proven v1.5 structure (R14, 3044us): 3 barriers/step, single-probe poll,
// padded h_sm, creg. ONLY delta this round: xw input projections are
// software-pipelined one step ahead into registers, so the per-step DRAM
// fetch no longer stalls warps 0-1 (h-chunk pollers 0-3) at step start.
__global__ void __launch_bounds__(512, 1) k_lstm(
    const float* __restrict__ Whf, const float* __restrict__ Whb,
    const float* __restrict__ c0)
{
    int dir = blockIdx.x >> 5;
    int cb  = blockIdx.x & 31;
    const float* W  = dir ? Whb : Whf;
    const float* xw = g_xw[dir];
    float* hsx = g_hsx[dir];

    int tid = threadIdx.x;
    int row = tid >> 3;            // 0..63 (gate row within slice)
    int kc  = tid & 7;
    int k0f = kc << 6;             // chunk start (logical float index)
    int g = row >> 4, d = row & 15;
    int D0 = cb << 4;              // first h-dim owned
    int grow = (g << 9) + D0 + d;  // global gate row

    // weights -> registers: 64 floats as 32 packed f32x2 words
    unsigned long long w[32];
    {
        const ulonglong2* wp = (const ulonglong2*)(W + grow * H2 + k0f);
        #pragma unroll
        for (int i = 0; i < 16; i++) { ulonglong2 v = wp[i]; w[2*i] = v.x; w[2*i+1] = v.y; }
    }

    __shared__ __align__(16) float h_sm[8 * CPAD];   // padded: conflict-free reads
    __shared__ float rowsum[64];
    __shared__ float pre_sm[64];

    float creg = 0.f;
    if (tid < 16) creg = c0[dir * H2 + D0 + tid];

    int pg = tid >> 4, pd = tid & 15;            // tid<64 prefetch mapping
    int pgrow = (pg << 9) + D0 + pd;
    int pchunk = tid >> 4, pj = tid & 15;        // tid<128 poller mapping

    // prologue: prefetch xw for step 0 into registers
    float nxt_pre = 0.f;
    if (tid < 64) {
        int xrow0 = dir ? (LSEQ - 1) : 0;
        nxt_pre = __ldg(&xw[xrow0 * G4 + pgrow]);
    }

    for (int t = 0; t < LSEQ; t++) {
        __syncthreads();                         // BAR0: guard smem reuse
        if (tid < 64) {
            pre_sm[tid] = nxt_pre;               // instant: from regs (step-t data)
            int tn = (t + 1 < LSEQ) ? (t + 1) : t;            // clamp (value unused at t=LSEQ-1)
            int xrown = dir ? (LSEQ - 1 - tn) : tn;
            nxt_pre = __ldg(&xw[xrown * G4 + pgrow]);         // t+1 fetch, whole step to land
        }
        if (tid < 128) {
            const uint4* src = (const uint4*)(hsx + t * H2) + tid;
            uint4 v;
            unsigned int it = 0;
            do {
                v = ldcg4(src);
                if (++it >= POLL_LIMIT) break;   // escape hatch (never taken normally)
            } while (v.x == SENT_BITS || v.y == SENT_BITS ||
                     v.z == SENT_BITS || v.w == SENT_BITS);
            *(uint4*)&h_sm[pchunk * CPAD + pj * 4] = v;
        }
        __syncthreads();                         // BAR1: h staged

        // partial dot: 64 MACs as 32 packed f32x2 FMAs against register weights
        unsigned long long acc0 = 0ull, acc1 = 0ull;
        const ulonglong2* hp = (const ulonglong2*)&h_sm[kc * CPAD];
        #pragma unroll
        for (int i = 0; i < 16; i++) {
            ulonglong2 hv = hp[i];
            fma2(acc0, w[2*i],   hv.x);
            fma2(acc1, w[2*i+1], hv.y);
        }
        float2 a0 = unpack2(acc0), a1 = unpack2(acc1);
        float s = (a0.x + a0.y) + (a1.x + a1.y);
        s += __shfl_xor_sync(0xffffffffu, s, 1);
        s += __shfl_xor_sync(0xffffffffu, s, 2);
        s += __shfl_xor_sync(0xffffffffu, s, 4);
        if (kc == 0) rowsum[row] = s;
        __syncthreads();                         // BAR2: rowsum ready

        if (tid < 16) {
            float pi = pre_sm[tid]      + rowsum[tid];
            float pf = pre_sm[16 + tid] + rowsum[16 + tid];
            float pgt= pre_sm[32 + tid] + rowsum[32 + tid];
            float po = pre_sm[48 + tid] + rowsum[48 + tid];
            float ii = sig_ap(pi), ff = sig_ap(pf), gg = tanh_ap(pgt), oo = sig_ap(po);
            creg = fmaf(ff, creg, ii * gg);
            float hh = oo * tanh_ap(creg);
            __stcg(&hsx[(t + 1) * H2 + D0 + tid], hh);   // publish (never NaN)
        }
    }
}

// ---------------- kernel 5: feats = [hf;hb] @ W_out^T + b_out ----------------
__global__ void __launch_bounds__(384) k_feats(const float* __restrict__ Wout,
                                               const float* __restrict__ bout)
{
    int t0 = blockIdx.x * 4;
    int tid = threadIdx.x;
    int wrp = tid >> 5;       // 0..11 = output tag
    int lane = tid & 31;
    __shared__ float W_sm[NT * 512];
    __shared__ float h_sm[512];
    float pacc[4] = {0.f, 0.f, 0.f, 0.f};

    for (int half = 0; half < 2; half++) {
        __syncthreads();
        #pragma unroll
        for (int i = 0; i < 16; i++) {
            int idx = tid + i * 384;
            W_sm[idx] = Wout[(idx >> 9) * 1024 + (half << 9) + (idx & 511)];
        }
        for (int tt = 0; tt < 4; tt++) {
            int t = t0 + tt;
            __syncthreads();
            int hrow = half ? (LSEQ - t) : (t + 1);    // hb[t] = hsx_b[L - t]
            const float* hsrc = g_hsx[half] + hrow * H2;
            for (int j = tid; j < 512; j += 384) h_sm[j] = hsrc[j];
            __syncthreads();
            float p = 0.f;
            #pragma unroll
            for (int k = lane; k < 512; k += 32) p += h_sm[k] * W_sm[wrp * 512 + k];
            pacc[tt] += p;
        }
    }
    #pragma unroll
    for (int tt = 0; tt < 4; tt++) {
        float p = pacc[tt];
        #pragma unroll
        for (int off = 16; off; off >>= 1) p += __shfl_down_sync(0xffffffffu, p, off);
        if (lane == 0) g_feats[(t0 + tt) * NT + wrp] = p + bout[wrp];
    }
}

// ---------------- kernel 6a: CRF chunk products (log-semiring scan) ----------
__global__ void k_crf_chunks(const float* __restrict__ trans) {
    int c = blockIdx.x;
    int tid = threadIdx.x;            // 0..143
    int i = tid / NT, j = tid - i * NT;
    __shared__ float Ma[NT * NT], Mb[NT * NT];
    float trow[NT];
    #pragma unroll
    for (int k = 0; k < NT; k++) trow[k] = trans[i * NT + k];

    int t0 = c * CRF_CHUNK;
    Ma[tid] = trow[j] + __ldg(&g_feats[t0 * NT + i]);   // M = A_{t0}
    __syncthreads();

    float* cur = Ma; float* nxt = Mb;
    for (int s = 1; s < CRF_CHUNK; s++) {
        float feat_i = __ldg(&g_feats[(t0 + s) * NT + i]);
        float m = -3.4e38f, vals[NT];
        #pragma unroll
        for (int k = 0; k < NT; k++) { vals[k] = trow[k] + cur[k * NT + j]; m = fmaxf(m, vals[k]); }
        float ssum = 0.f;
        #pragma unroll
        for (int k = 0; k < NT; k++) ssum += __expf(vals[k] - m);
        nxt[tid] = feat_i + m + __logf(ssum);
        __syncthreads();
        float* tmp = cur; cur = nxt; nxt = tmp;
    }
    g_crf_m[c * NT * NT + tid] = cur[tid];
}

// ---------------- kernel 6b: fold chunk matrices into fv, terminal LSE -------
__global__ void k_crf_fold(const float* __restrict__ trans, float* __restrict__ out) {
    int lane = threadIdx.x;
    bool act = lane < NT;
    __shared__ float fv[NT];
    if (act) fv[lane] = (lane == START_TAG) ? 0.f : NEGV;
    __syncwarp();
    for (int c = 0; c < NCHUNK; c++) {
        float nv = 0.f;
        if (act) {
            const float* M = &g_crf_m[c * NT * NT + lane * NT];   // row `lane`
            float m = -3.4e38f, vals[NT];
            #pragma unroll
            for (int j = 0; j < NT; j++) { vals[j] = __ldg(&M[j]) + fv[j]; m = fmaxf(m, vals[j]); }
            float s = 0.f;
            #pragma unroll
            for (int j = 0; j < NT; j++) s += __expf(vals[j] - m);
            nv = m + __logf(s);
        }
        __syncwarp();
        if (act) fv[lane] = nv;
        __syncwarp();
    }
    if (lane == 0) {
        float m = -3.4e38f, vals[NT];
        #pragma unroll
        for (int j = 0; j < NT; j++) { vals[j] = fv[j] + trans[STOP_TAG * NT + j]; m = fmaxf(m, vals[j]); }
        float s = 0.f;
        #pragma unroll
        for (int j = 0; j < NT; j++) s += __expf(vals[j] - m);
        out[0] = m + __logf(s);
    }
}

// ---------------- launcher ----------------------------------------------------
extern "C" void kernel_launch(void* const* d_in, const int* in_sizes, int n_in,
                              void* d_out, int out_size)
{
    const int*   sentence = (const int*)  d_in[0];
    const float* emb      = (const float*)d_in[1];
    const float* W_ih_f   = (const float*)d_in[2];
    const float* W_hh_f   = (const float*)d_in[3];
    const float* b_f      = (const float*)d_in[4];
    const float* W_ih_b   = (const float*)d_in[5];
    const float* W_hh_b   = (const float*)d_in[6];
    const float* b_b      = (const float*)d_in[7];
    const float* W_out    = (const float*)d_in[8];
    const float* b_out    = (const float*)d_in[9];
    const float* trans    = (const float*)d_in[10];
    const float* h0       = (const float*)d_in[11];
    const float* c0       = (const float*)d_in[12];
    float* out = (float*)d_out;

    (void)in_sizes; (void)n_in; (void)out_size;

    // 1. sentinel-fill h history (both dirs) + write h0 into slot 0
    k_init_hsx<<<(2 * (LSEQ + 1) * H2 + 255) / 256, 256>>>(h0);
    // 2. embedding gather
    k_gather<<<(LSEQ * (EDIM / 4)) / 256, 256>>>(sentence, emb);
    // 3. input projections for both directions
    k_gemm_xw<<<dim3(32, 32, 2), dim3(16, 16)>>>(W_ih_f, b_f, W_ih_b, b_b);
    // 4. persistent bidirectional recurrence (64 co-resident CTAs)
    k_lstm<<<64, 512>>>(W_hh_f, W_hh_b, c0);
    // 5. output projection
    k_feats<<<LSEQ / 4, 384>>>(W_out, b_out);
    // 6. CRF forward: parallel chunk products, then sequential fold
    k_crf_chunks<<<NCHUNK, NT * NT>>>(trans);
    k_crf_fold<<<1, 32>>>(trans, out);
}